// round 12
// baseline (speedup 1.0000x reference)
#include <cuda_runtime.h>

#define TINYV 1.1920929e-7f        // float32 machine eps = np.finfo(float32).eps
#define CGRID 0.49951171875f       // 0.5 - 2^-11, exact in fp32

typedef unsigned long long u64;

// eps (8 floats = 4 packed f32x2 pairs, little-endian == pk(lo,hi)) and beta,
// copied in kernel_launch via cudaMemcpyToSymbolAsync (D2D, graph-capturable).
__constant__ u64   c_eps2[4];
__constant__ float c_beta;

// ---- packed f32x2 helpers (sm_103a). Per-lane IEEE RN: bit-identical to scalar. ----
__device__ __forceinline__ u64 pk(float lo, float hi) {
    u64 r; asm("mov.b64 %0, {%1, %2};" : "=l"(r) : "f"(lo), "f"(hi)); return r;
}
__device__ __forceinline__ void upk(u64 v, float& lo, float& hi) {
    asm("mov.b64 {%0, %1}, %2;" : "=f"(lo), "=f"(hi) : "l"(v));
}
__device__ __forceinline__ u64 add2(u64 a, u64 b) {
    u64 r; asm("add.rn.f32x2 %0, %1, %2;" : "=l"(r) : "l"(a), "l"(b)); return r;
}
__device__ __forceinline__ u64 mul2(u64 a, u64 b) {
    u64 r; asm("mul.rn.f32x2 %0, %1, %2;" : "=l"(r) : "l"(a), "l"(b)); return r;
}
__device__ __forceinline__ u64 fma2(u64 a, u64 b, u64 c) {
    u64 r; asm("fma.rn.f32x2 %0, %1, %2, %3;" : "=l"(r) : "l"(a), "l"(b), "l"(c)); return r;
}

// packed-pair constants (bit patterns of (v, v))
#define H2C  0x3F0000003F000000ULL   // (+0.5, +0.5)
#define NH2C 0xBF000000BF000000ULL   // (-0.5, -0.5)
#define M1C  0xBF800000BF800000ULL   // (-1.0, -1.0)
#define M4C  0xC0800000C0800000ULL   // (-4.0, -4.0)
#define QC   0x3E8000003E800000ULL   // (0.25, 0.25)
#define S4C  0x4080000040800000ULL   // (4.0, 4.0)
#define S16C 0x4180000041800000ULL   // (16.0, 16.0)

// -copysign(TINY, x) as a single logic op: (~sign(x)) | bits(2^-23)
__device__ __forceinline__ float negtiny(float x) {
    return __int_as_float(((__float_as_int(x) & 0x80000000) ^ 0x80000000) | 0x34000000);
}

// Literal custom_round, 8-wide with packed adds. Sequence identical to
// floor((x - copysign(TINY,x)) + 0.5) per lane.
__device__ __forceinline__ void cround8_exact(const float x[8], float f[8]) {
#pragma unroll
    for (int p = 0; p < 4; p++) {
        float a0 = x[2*p], a1 = x[2*p+1];
        u64 v = add2(add2(pk(a0, a1), pk(negtiny(a0), negtiny(a1))), H2C);
        float v0, v1; upk(v, v0, v1);
        f[2*p] = floorf(v0); f[2*p+1] = floorf(v1);
    }
}
// Grid custom_round (valid |x| < 2 on >=1/8 grid; validated rel_err=0 in R5/R7):
__device__ __forceinline__ void cround8_grid(const float x[8], float f[8]) {
#pragma unroll
    for (int p = 0; p < 4; p++) {
        float a0 = x[2*p], a1 = x[2*p+1];
        u64 v = add2(pk(a0, a1), pk(copysignf(CGRID, a0), copysignf(CGRID, a1)));
        float v0, v1; upk(v, v0, v1);
        f[2*p] = truncf(v0); f[2*p+1] = truncf(v1);
    }
}

// first-occurrence argmax scan: sel[j] = first j with |e_j|==m; step = sign(e_k),
// fallback (m==0) step = copysign(1, -xa0) (== reference rule).
__device__ __forceinline__ void scanfn(const float e[8], float m, float xa0,
                                       bool sel[8], float& step) {
    bool seen = false;
#pragma unroll
    for (int j = 0; j < 8; j++) {
        bool eq = (fabsf(e[j]) == m);
        sel[j] = eq && !seen;
        seen = seen || eq;
    }
    float t = e[0];
#pragma unroll
    for (int j = 1; j < 8; j++) t = sel[j] ? e[j] : t;
    t = (m == 0.0f) ? -xa0 : t;
    step = copysignf(1.0f, t);
}

// ---------- full-replication branch (layer-0 only, R7-validated verbatim) ----------
template<bool SHIFTED>
__device__ __forceinline__ float e8_branch_full(const float xa[8], const u64 xo2[4],
                                                float yc[8]) {
    float f[8], e[8];
    cround8_exact(xa, f);
#pragma unroll
    for (int p = 0; p < 4; p++) {
        u64 e2 = fma2(pk(f[2*p], f[2*p+1]), M1C, pk(xa[2*p], xa[2*p+1]));
        upk(e2, e[2*p], e[2*p+1]);
    }
    u64 s = add2(add2(pk(f[0],f[1]), pk(f[2],f[3])),
                 add2(pk(f[4],f[5]), pk(f[6],f[7])));
    float sl, sh; upk(s, sl, sh);
    bool odd = (((int)(sl + sh)) & 1) != 0;

    float m = fmaxf(fmaxf(fmaxf(fabsf(e[0]),fabsf(e[1])),fmaxf(fabsf(e[2]),fabsf(e[3]))),
                    fmaxf(fmaxf(fabsf(e[4]),fabsf(e[5])),fmaxf(fabsf(e[6]),fabsf(e[7]))));
    bool sel[8]; float step;
    scanfn(e, m, xa[0], sel, step);

#pragma unroll
    for (int p = 0; p < 4; p++) {
        float b0, b1;
        if (SHIFTED) { u64 b2 = add2(pk(f[2*p], f[2*p+1]), H2C); upk(b2, b0, b1); }
        else         { b0 = f[2*p]; b1 = f[2*p+1]; }
        yc[2*p]   = (odd && sel[2*p])   ? (b0 + step) : b0;
        yc[2*p+1] = (odd && sel[2*p+1]) ? (b1 + step) : b1;
    }
    float r[8];
#pragma unroll
    for (int p = 0; p < 4; p++) {
        u64 r2 = fma2(pk(yc[2*p], yc[2*p+1]), M1C, xo2[p]);
        upk(r2, r[2*p], r[2*p+1]);
    }
    float d = r[0] * r[0];
#pragma unroll
    for (int j = 1; j < 8; j++) d = fmaf(r[j], r[j], d);
    return d;
}

__device__ __forceinline__ void cp_e8_full(const float x[8], float y[8]) {
    u64 x2[4];
    float xs[8];
#pragma unroll
    for (int p = 0; p < 4; p++) {
        x2[p] = pk(x[2*p], x[2*p+1]);
        u64 s2 = add2(x2[p], NH2C);
        upk(s2, xs[2*p], xs[2*p+1]);
    }
    float yA[8], yB[8];
    float dA = e8_branch_full<false>(x,  x2, yA);
    float dB = e8_branch_full<true >(xs, x2, yB);
    bool pickA = dA < dB;
#pragma unroll
    for (int j = 0; j < 8; j++) y[j] = pickA ? yA[j] : yB[j];
}

// ---------- closed-form variant: grid inputs only (validated rel_err=0 in R6) ----------
// d = sum e^2 (+ 1 - 2*max|e| if odd). Exact dyadics on grid inputs -> bit-equal
// to the reference's sequential distance. Only the PICKED candidate is assembled.
template<bool GR>
__device__ __forceinline__ void cp_e8_closed(const float x[8], float y[8]) {
    u64 x2[4], xs2[4];
    float xs[8];
#pragma unroll
    for (int p = 0; p < 4; p++) {
        x2[p] = pk(x[2*p], x[2*p+1]);
        xs2[p] = add2(x2[p], NH2C);
        upk(xs2[p], xs[2*p], xs[2*p+1]);
    }

    float fA[8], fB[8];
    if (GR) { cround8_grid(x, fA); cround8_grid(xs, fB); }
    else    { cround8_exact(x, fA); cround8_exact(xs, fB); }

    float eA[8], eB[8];
#pragma unroll
    for (int p = 0; p < 4; p++) {
        u64 a2 = fma2(pk(fA[2*p], fA[2*p+1]), M1C, x2[p]);
        upk(a2, eA[2*p], eA[2*p+1]);
        u64 b2 = fma2(pk(fB[2*p], fB[2*p+1]), M1C, xs2[p]);
        upk(b2, eB[2*p], eB[2*p+1]);
    }

    u64 sa = add2(add2(pk(fA[0],fA[1]), pk(fA[2],fA[3])),
                  add2(pk(fA[4],fA[5]), pk(fA[6],fA[7])));
    u64 sb = add2(add2(pk(fB[0],fB[1]), pk(fB[2],fB[3])),
                  add2(pk(fB[4],fB[5]), pk(fB[6],fB[7])));
    float sal, sah, sbl, sbh;
    upk(sa, sal, sah); upk(sb, sbl, sbh);
    bool oddA = (((int)(sal + sah)) & 1) != 0;
    bool oddB = (((int)(sbl + sbh)) & 1) != 0;

    float mA = fmaxf(fmaxf(fmaxf(fabsf(eA[0]),fabsf(eA[1])),fmaxf(fabsf(eA[2]),fabsf(eA[3]))),
                     fmaxf(fmaxf(fabsf(eA[4]),fabsf(eA[5])),fmaxf(fabsf(eA[6]),fabsf(eA[7]))));
    float mB = fmaxf(fmaxf(fmaxf(fabsf(eB[0]),fabsf(eB[1])),fmaxf(fabsf(eB[2]),fabsf(eB[3]))),
                     fmaxf(fmaxf(fabsf(eB[4]),fabsf(eB[5])),fmaxf(fabsf(eB[6]),fabsf(eB[7]))));

    bool selA[8], selB[8];
    float stepA, stepB;
    scanfn(eA, mA, x[0],  selA, stepA);
    scanfn(eB, mB, xs[0], selB, stepB);

    float dA = eA[0]*eA[0];
#pragma unroll
    for (int j = 1; j < 8; j++) dA = fmaf(eA[j], eA[j], dA);
    dA = oddA ? (dA + fmaf(-2.0f, mA, 1.0f)) : dA;

    float dB = eB[0]*eB[0];
#pragma unroll
    for (int j = 1; j < 8; j++) dB = fmaf(eB[j], eB[j], dB);
    dB = oddB ? (dB + fmaf(-2.0f, mB, 1.0f)) : dB;

    bool pickA = dA < dB;          // tie -> B (jnp.where(d0 < d1, y0, y1))

    float h   = pickA ? 0.0f : 0.5f;
    float stp = pickA ? stepA : stepB;
    bool oddp = pickA ? oddA : oddB;
    stp = oddp ? stp : 0.0f;       // fold parity; +-0 outcomes value-identical
#pragma unroll
    for (int j = 0; j < 8; j++) {
        float fj = pickA ? fA[j] : fB[j];
        bool  sj = pickA ? selA[j] : selB[j];
        float base = fj + h;
        y[j] = sj ? (base + stp) : base;
    }
}

__global__ __launch_bounds__(128)   // natural regs — forcing a cap spills (R8/R10)
void LatticeQuantizer_kernel(const float* __restrict__ x,
                             float* __restrict__ out, int N)
{
    int i = blockIdx.x * blockDim.x + threadIdx.x;
    if (i >= N) return;

    float beta = c_beta;

    float4 va = ((const float4*)x)[2 * i];
    float4 vb = ((const float4*)x)[2 * i + 1];
    float xl[8] = {va.x, va.y, va.z, va.w, vb.x, vb.y, vb.z, vb.w};
    if (beta != 1.0f) {             // uniform branch; x/1.0 == x exactly
#pragma unroll
        for (int j = 0; j < 8; j++) xl[j] = __fdiv_rn(xl[j], beta);
    }

    u64 xh2[4];

#pragma unroll
    for (int m = 0; m < 3; m++) {
        // ---- encode: yq = closest_point_E8(xl + eps) ----
        float xe[8], yq[8];
#pragma unroll
        for (int p = 0; p < 4; p++) {
            u64 t = add2(pk(xl[2*p], xl[2*p+1]), c_eps2[p]);
            upk(t, xe[2*p], xe[2*p+1]);
        }
        // layer 0: continuous -> full replication.
        // layer 1: grid input, |xe| can exceed 2 -> closed form + exact cround (R6-validated).
        // layer 2: grid input, |xe| < 2 -> closed form + grid cround (composition-safe).
        if (m == 0)      cp_e8_full(xe, yq);
        else if (m == 1) cp_e8_closed<false>(xe, yq);
        else             cp_e8_closed<true >(xe, yq);

        // ---- acc = yq @ G_inv via exact forward substitution (acc @ Gm = yq) ----
        float a[8];
        a[0] = 0.5f * yq[0];
#pragma unroll
        for (int j = 1; j < 7; j++) a[j] = a[j - 1] + yq[j];
        float s06 = ((a[0] + a[1]) + (a[2] + a[3])) + ((a[4] + a[5]) + a[6]);
        a[7] = fmaf(2.0f, yq[7], -s06);

        // ---- b = custom_round(fmod(acc,4)): quarter-int in (-4,4), ties at
        //      +-2.5/+-3.5 round half-up -> exact cround required ----
        float r8[8], bv[8];
#pragma unroll
        for (int j = 0; j < 8; j++)
            r8[j] = fmaf(-4.0f, truncf(a[j] * 0.25f), a[j]);  // == fmodf(a,4) exactly
        cround8_exact(r8, bv);

        // ---- next layer input: xl = yq * 0.25 (packed, exact) ----
#pragma unroll
        for (int p = 0; p < 4; p++) {
            u64 t = mul2(pk(yq[2*p], yq[2*p+1]), QC);
            upk(t, xl[2*p], xl[2*p+1]);
        }

        // ---- Gb = b @ G.T, sparse exact form ----
        float gb[8];
        {
            float h = 0.5f * bv[7];
            gb[0] = fmaf(2.0f, bv[0], -bv[1]) + h;
#pragma unroll
            for (int j = 1; j < 6; j++) gb[j] = (bv[j] - bv[j + 1]) + h;
            gb[6] = bv[6] + h;
            gb[7] = h;
        }

        // ---- x_i = Gb - 4*closest_point_E8(Gb/4);  xh += 4^m * x_i ----
        // gq in [-0.75, 1.875], branch-B in [-1.25, 1.375] -> closed + grid cround
        // (R6-validated).
        float gq[8], cpv[8];
        u64 gb2[4];
#pragma unroll
        for (int p = 0; p < 4; p++) {
            gb2[p] = pk(gb[2*p], gb[2*p+1]);
            u64 t = mul2(gb2[p], QC);
            upk(t, gq[2*p], gq[2*p+1]);
        }
        cp_e8_closed<true>(gq, cpv);

#pragma unroll
        for (int p = 0; p < 4; p++) {
            u64 xi = fma2(pk(cpv[2*p], cpv[2*p+1]), M4C, gb2[p]);
            if (m == 0)      xh2[p] = xi;
            else if (m == 1) xh2[p] = fma2(xi, S4C,  xh2[p]);   // exact dyadics
            else             xh2[p] = fma2(xi, S16C, xh2[p]);
        }
    }

    u64 bb = pk(beta, beta);
    float o[8];
#pragma unroll
    for (int p = 0; p < 4; p++) {
        u64 t = mul2(xh2[p], bb);
        upk(t, o[2*p], o[2*p+1]);
    }
    float4 o0 = {o[0], o[1], o[2], o[3]};
    float4 o1 = {o[4], o[5], o[6], o[7]};
    ((float4*)out)[2 * i]     = o0;
    ((float4*)out)[2 * i + 1] = o1;
}

extern "C" void kernel_launch(void* const* d_in, const int* in_sizes, int n_in,
                              void* d_out, int out_size) {
    const float* x = (const float*)d_in[0];
    float* out = (float*)d_out;

    // beta + eps into constant bank (D2D async copies: graph-capturable, no alloc)
    cudaMemcpyToSymbolAsync(c_beta, d_in[1], sizeof(float), 0,
                            cudaMemcpyDeviceToDevice, 0);
    cudaMemcpyToSymbolAsync(c_eps2, d_in[4], 8 * sizeof(float), 0,
                            cudaMemcpyDeviceToDevice, 0);

    int N = in_sizes[0] / 8;
    int threads = 128;
    int blocks = (N + threads - 1) / threads;
    LatticeQuantizer_kernel<<<blocks, threads>>>(x, out, N);
}

// round 14
// speedup vs baseline: 1.1115x; 1.1115x over previous
#include <cuda_runtime.h>

#define TINYV 1.1920929e-7f        // float32 machine eps = np.finfo(float32).eps

typedef unsigned long long u64;

// eps (8 floats = 4 packed f32x2 pairs, little-endian == pk(lo,hi)) and beta,
// copied in kernel_launch via cudaMemcpyToSymbolAsync (D2D, graph-capturable).
__constant__ u64   c_eps2[4];
__constant__ float c_beta;

// ---- packed f32x2 helpers (sm_103a). Per-lane IEEE RN: bit-identical to scalar. ----
__device__ __forceinline__ u64 pk(float lo, float hi) {
    u64 r; asm("mov.b64 %0, {%1, %2};" : "=l"(r) : "f"(lo), "f"(hi)); return r;
}
__device__ __forceinline__ void upk(u64 v, float& lo, float& hi) {
    asm("mov.b64 {%0, %1}, %2;" : "=f"(lo), "=f"(hi) : "l"(v));
}
__device__ __forceinline__ u64 add2(u64 a, u64 b) {
    u64 r; asm("add.rn.f32x2 %0, %1, %2;" : "=l"(r) : "l"(a), "l"(b)); return r;
}
__device__ __forceinline__ u64 mul2(u64 a, u64 b) {
    u64 r; asm("mul.rn.f32x2 %0, %1, %2;" : "=l"(r) : "l"(a), "l"(b)); return r;
}
__device__ __forceinline__ u64 fma2(u64 a, u64 b, u64 c) {
    u64 r; asm("fma.rn.f32x2 %0, %1, %2, %3;" : "=l"(r) : "l"(a), "l"(b), "l"(c)); return r;
}

// packed-pair constants (bit patterns of (v, v))
#define H2C   0x3F0000003F000000ULL   // (+0.5, +0.5)
#define NH2C  0xBF000000BF000000ULL   // (-0.5, -0.5)
#define M1C   0xBF800000BF800000ULL   // (-1.0, -1.0)
#define M4C   0xC0800000C0800000ULL   // (-4.0, -4.0)
#define QC    0x3E8000003E800000ULL   // (0.25, 0.25)
#define S4C   0x4080000040800000ULL   // (4.0, 4.0)
#define S16C  0x4180000041800000ULL   // (16.0, 16.0)
#define MG2C  0x4B4000004B400000ULL   // (1.5*2^23, 1.5*2^23) round-to-int magic
#define NMG2C 0xCB400000CB400000ULL   // (-1.5*2^23, -1.5*2^23)

// -copysign(TINY, x): (~sign(x)) | bits(2^-23)
__device__ __forceinline__ float negtiny(float x) {
    return __int_as_float(((__float_as_int(x) & 0x80000000) ^ 0x80000000) | 0x34000000);
}
// grid bias: -copysign(2^-11, x)  (ties -> toward zero; valid grid |x|<2)
__device__ __forceinline__ float gbias(float x) {
    return __int_as_float(((__float_as_int(x) & 0x80000000) ^ 0x80000000) | 0x3A000000);
}
// exact tie-law bias: +2^-11 if (x<0 || x>=2) else -2^-11.
// Reference law (derived from floor(x - sign(x)*TINY + 0.5) under RNE):
//   ties round toward +inf for negatives (-> toward zero) and positives >= 2
//   (TINY absorbed); toward -inf for 0 <= x < 2 (exact subtract).
// Condition == unsigned bits(x) >= 0x40000000 (positives >= 2, and ALL
// negatives since their bits >= 0x80000000). No overflow (R12 bug fixed).
__device__ __forceinline__ float ebias(float x) {
    unsigned b = (unsigned)__float_as_int(x);
    return __uint_as_float((b >= 0x40000000u) ? 0x3A000000u : 0xBA000000u);
}

// RND: 0 = literal floor path (continuous inputs, layer-0 only)
//      1 = magic round, exact tie law   (grid inputs, any magnitude: L1 encode, b-round)
//      2 = magic round, grid tie law    (grid inputs, |x| < 2: L2 encode, decode)
template<int RND>
__device__ __forceinline__ void cround8p(const float xa[8], const u64 xa2[4], u64 f2[4]) {
#pragma unroll
    for (int p = 0; p < 4; p++) {
        float a0 = xa[2*p], a1 = xa[2*p+1];
        if (RND == 0) {
            u64 v = add2(add2(xa2[p], pk(negtiny(a0), negtiny(a1))), H2C);
            float v0, v1; upk(v, v0, v1);
            f2[p] = pk(floorf(v0), floorf(v1));
        } else {
            u64 b2 = (RND == 1) ? pk(ebias(a0), ebias(a1))
                                : pk(gbias(a0), gbias(a1));
            // (x + bias + MAGIC) - MAGIC : RN-to-int, ties pre-broken by bias.
            f2[p] = add2(add2(add2(xa2[p], b2), MG2C), NMG2C);
        }
    }
}

// first-occurrence argmax scan (R3-proven): sel[j] = first j with |e_j|==m;
// step = sign(e_k), fallback (m==0) step = copysign(1, -xa0).
__device__ __forceinline__ void scanfn(const float e[8], float m, float xa0,
                                       bool sel[8], float& step) {
    bool seen = false;
#pragma unroll
    for (int j = 0; j < 8; j++) {
        bool eq = (fabsf(e[j]) == m);
        sel[j] = eq && !seen;
        seen = seen || eq;
    }
    float t = e[0];
#pragma unroll
    for (int j = 1; j < 8; j++) t = sel[j] ? e[j] : t;
    t = (m == 0.0f) ? -xa0 : t;
    step = copysignf(1.0f, t);
}

// One branch of closest_point_E8, full replication (R7-validated structure).
template<int RND, bool SHIFTED>
__device__ __forceinline__ float e8_branch(const float xa[8], const u64 xa2[4],
                                           const u64 xo2[4], float yc[8]) {
    u64 f2[4];
    cround8p<RND>(xa, xa2, f2);

    float f[8], e[8];
#pragma unroll
    for (int p = 0; p < 4; p++) {
        upk(f2[p], f[2*p], f[2*p+1]);
        u64 e2 = fma2(f2[p], M1C, xa2[p]);   // e = xa - f (single-rounded subtract)
        upk(e2, e[2*p], e[2*p+1]);
    }

    // parity of sum(f): packed tree on native f2 (exact small integers)
    u64 s = add2(add2(f2[0], f2[1]), add2(f2[2], f2[3]));
    float sl, sh; upk(s, sl, sh);
    bool odd = (((int)(sl + sh)) & 1) != 0;

    // max |e| (FMNMX absorbs |.|)
    float m = fmaxf(fmaxf(fmaxf(fabsf(e[0]),fabsf(e[1])),fmaxf(fabsf(e[2]),fabsf(e[3]))),
                    fmaxf(fmaxf(fabsf(e[4]),fabsf(e[5])),fmaxf(fabsf(e[6]),fabsf(e[7]))));

    bool sel[8]; float step;
    scanfn(e, m, xa[0], sel, step);

    // candidate assembly (base = f (+0.5 if SHIFTED), flip one coord if odd)
#pragma unroll
    for (int p = 0; p < 4; p++) {
        float b0, b1;
        if (SHIFTED) { u64 b2 = add2(f2[p], H2C); upk(b2, b0, b1); }
        else         { b0 = f[2*p]; b1 = f[2*p+1]; }
        yc[2*p]   = (odd && sel[2*p])   ? (b0 + step) : b0;
        yc[2*p+1] = (odd && sel[2*p+1]) ? (b1 + step) : b1;
    }

    // distance vs ORIGINAL x: packed residuals, scalar sequential sum (reference order)
    float r[8];
#pragma unroll
    for (int p = 0; p < 4; p++) {
        u64 r2 = fma2(pk(yc[2*p], yc[2*p+1]), M1C, xo2[p]);
        upk(r2, r[2*p], r[2*p+1]);
    }
    float d = r[0] * r[0];
#pragma unroll
    for (int j = 1; j < 8; j++) d = fmaf(r[j], r[j], d);
    return d;
}

template<int RND>
__device__ __forceinline__ void cp_e8(const float x[8], float y[8]) {
    u64 x2[4], xs2[4];
    float xs[8];
#pragma unroll
    for (int p = 0; p < 4; p++) {
        x2[p] = pk(x[2*p], x[2*p+1]);
        xs2[p] = add2(x2[p], NH2C);            // x - 0.5, packed (== scalar)
        upk(xs2[p], xs[2*p], xs[2*p+1]);
    }
    float yA[8], yB[8];
    float dA = e8_branch<RND, false>(x,  x2,  x2, yA);
    float dB = e8_branch<RND, true >(xs, xs2, x2, yB);
    bool pickA = dA < dB;                      // tie -> B (jnp.where(d0 < d1, y0, y1))
#pragma unroll
    for (int j = 0; j < 8; j++) y[j] = pickA ? yA[j] : yB[j];
}

__global__ __launch_bounds__(128)   // natural regs — forced caps spill (R8/R10)
void LatticeQuantizer_kernel(const float* __restrict__ x,
                             float* __restrict__ out, int N)
{
    int i = blockIdx.x * blockDim.x + threadIdx.x;
    if (i >= N) return;

    float beta = c_beta;

    float4 va = ((const float4*)x)[2 * i];
    float4 vb = ((const float4*)x)[2 * i + 1];
    float xl[8] = {va.x, va.y, va.z, va.w, vb.x, vb.y, vb.z, vb.w};
    if (beta != 1.0f) {             // uniform branch; x/1.0 == x exactly
#pragma unroll
        for (int j = 0; j < 8; j++) xl[j] = __fdiv_rn(xl[j], beta);
    }

    u64 xh2[4];

#pragma unroll
    for (int m = 0; m < 3; m++) {
        // ---- encode: yq = closest_point_E8(xl + eps) ----
        float xe[8], yq[8];
#pragma unroll
        for (int p = 0; p < 4; p++) {
            u64 t = add2(pk(xl[2*p], xl[2*p+1]), c_eps2[p]);
            upk(t, xe[2*p], xe[2*p+1]);
        }
        // layer 0: continuous -> literal floor path.
        // layer 1: 1/8-grid, |xe| can exceed 2 -> magic + exact tie law.
        // layer 2: 1/8-grid, |xe| < 2 -> magic + grid tie law (R5/R7-validated).
        if (m == 0)      cp_e8<0>(xe, yq);
        else if (m == 1) cp_e8<1>(xe, yq);
        else             cp_e8<2>(xe, yq);

        // ---- acc = yq @ G_inv via exact forward substitution (acc @ Gm = yq) ----
        float a[8];
        a[0] = 0.5f * yq[0];
#pragma unroll
        for (int j = 1; j < 7; j++) a[j] = a[j - 1] + yq[j];
        float s06 = ((a[0] + a[1]) + (a[2] + a[3])) + ((a[4] + a[5]) + a[6]);
        a[7] = fmaf(2.0f, yq[7], -s06);

        // ---- b = custom_round(fmod(acc,4)): r quarter-int in (-4,4);
        //      ties at +-0.5..+-3.5 follow the exact tie law -> magic RND=1 ----
        float r8[8], bv[8];
        u64 r82[4], bv2[4];
#pragma unroll
        for (int j = 0; j < 8; j++)
            r8[j] = fmaf(-4.0f, truncf(a[j] * 0.25f), a[j]);  // == fmodf(a,4) exactly
#pragma unroll
        for (int p = 0; p < 4; p++) r82[p] = pk(r8[2*p], r8[2*p+1]);
        cround8p<1>(r8, r82, bv2);
#pragma unroll
        for (int p = 0; p < 4; p++) upk(bv2[p], bv[2*p], bv[2*p+1]);

        // ---- next layer input: xl = yq * 0.25 (packed, exact) ----
#pragma unroll
        for (int p = 0; p < 4; p++) {
            u64 t = mul2(pk(yq[2*p], yq[2*p+1]), QC);
            upk(t, xl[2*p], xl[2*p+1]);
        }

        // ---- Gb = b @ G.T, sparse exact form ----
        float gb[8];
        {
            float h = 0.5f * bv[7];
            gb[0] = fmaf(2.0f, bv[0], -bv[1]) + h;
#pragma unroll
            for (int j = 1; j < 6; j++) gb[j] = (bv[j] - bv[j + 1]) + h;
            gb[6] = bv[6] + h;
            gb[7] = h;
        }

        // ---- x_i = Gb - 4*closest_point_E8(Gb/4);  xh += 4^m * x_i ----
        // gq in [-0.75, 1.875], branch-B in [-1.25, 1.375] -> grid tie law.
        float gq[8], cpv[8];
        u64 gb2[4];
#pragma unroll
        for (int p = 0; p < 4; p++) {
            gb2[p] = pk(gb[2*p], gb[2*p+1]);
            u64 t = mul2(gb2[p], QC);
            upk(t, gq[2*p], gq[2*p+1]);
        }
        cp_e8<2>(gq, cpv);

#pragma unroll
        for (int p = 0; p < 4; p++) {
            u64 xi = fma2(pk(cpv[2*p], cpv[2*p+1]), M4C, gb2[p]);
            if (m == 0)      xh2[p] = xi;
            else if (m == 1) xh2[p] = fma2(xi, S4C,  xh2[p]);   // exact dyadics
            else             xh2[p] = fma2(xi, S16C, xh2[p]);
        }
    }

    u64 bb = pk(beta, beta);
    float o[8];
#pragma unroll
    for (int p = 0; p < 4; p++) {
        u64 t = mul2(xh2[p], bb);
        upk(t, o[2*p], o[2*p+1]);
    }
    float4 o0 = {o[0], o[1], o[2], o[3]};
    float4 o1 = {o[4], o[5], o[6], o[7]};
    ((float4*)out)[2 * i]     = o0;
    ((float4*)out)[2 * i + 1] = o1;
}

extern "C" void kernel_launch(void* const* d_in, const int* in_sizes, int n_in,
                              void* d_out, int out_size) {
    const float* x = (const float*)d_in[0];
    float* out = (float*)d_out;

    // beta + eps into constant bank (D2D async copies: graph-capturable, no alloc)
    cudaMemcpyToSymbolAsync(c_beta, d_in[1], sizeof(float), 0,
                            cudaMemcpyDeviceToDevice, 0);
    cudaMemcpyToSymbolAsync(c_eps2, d_in[4], 8 * sizeof(float), 0,
                            cudaMemcpyDeviceToDevice, 0);

    int N = in_sizes[0] / 8;
    int threads = 128;
    int blocks = (N + threads - 1) / threads;
    LatticeQuantizer_kernel<<<blocks, threads>>>(x, out, N);
}

// round 15
// speedup vs baseline: 1.2346x; 1.1107x over previous
#include <cuda_runtime.h>

#define TINYV 1.1920929e-7f        // float32 machine eps = np.finfo(float32).eps

typedef unsigned long long u64;

// eps (8 floats = 4 packed f32x2 pairs, little-endian == pk(lo,hi)) and beta,
// copied in kernel_launch via cudaMemcpyToSymbolAsync (D2D, graph-capturable).
__constant__ u64   c_eps2[4];
__constant__ float c_beta;

// ---- packed f32x2 helpers (sm_103a). Per-lane IEEE RN: bit-identical to scalar. ----
__device__ __forceinline__ u64 pk(float lo, float hi) {
    u64 r; asm("mov.b64 %0, {%1, %2};" : "=l"(r) : "f"(lo), "f"(hi)); return r;
}
__device__ __forceinline__ void upk(u64 v, float& lo, float& hi) {
    asm("mov.b64 {%0, %1}, %2;" : "=f"(lo), "=f"(hi) : "l"(v));
}
__device__ __forceinline__ u64 add2(u64 a, u64 b) {
    u64 r; asm("add.rn.f32x2 %0, %1, %2;" : "=l"(r) : "l"(a), "l"(b)); return r;
}
__device__ __forceinline__ u64 mul2(u64 a, u64 b) {
    u64 r; asm("mul.rn.f32x2 %0, %1, %2;" : "=l"(r) : "l"(a), "l"(b)); return r;
}
__device__ __forceinline__ u64 fma2(u64 a, u64 b, u64 c) {
    u64 r; asm("fma.rn.f32x2 %0, %1, %2, %3;" : "=l"(r) : "l"(a), "l"(b), "l"(c)); return r;
}

// packed-pair constants (bit patterns of (v, v))
#define H2C   0x3F0000003F000000ULL   // (+0.5, +0.5)
#define NH2C  0xBF000000BF000000ULL   // (-0.5, -0.5)
#define M1C   0xBF800000BF800000ULL   // (-1.0, -1.0)
#define M4C   0xC0800000C0800000ULL   // (-4.0, -4.0)
#define QC    0x3E8000003E800000ULL   // (0.25, 0.25)
#define S4C   0x4080000040800000ULL   // (4.0, 4.0)
#define S16C  0x4180000041800000ULL   // (16.0, 16.0)
#define MG2C  0x4B4000004B400000ULL   // (1.5*2^23, 1.5*2^23) round-to-int magic
#define NMG2C 0xCB400000CB400000ULL   // (-1.5*2^23, -1.5*2^23)
#define MAGF  12582912.0f             // 1.5*2^23

// -copysign(TINY, x): (~sign(x)) | bits(2^-23)
__device__ __forceinline__ float negtiny(float x) {
    return __int_as_float(((__float_as_int(x) & 0x80000000) ^ 0x80000000) | 0x34000000);
}
// grid bias: -copysign(2^-11, x)  (ties -> toward zero; valid grid |x|<2)
__device__ __forceinline__ float gbias(float x) {
    return __int_as_float(((__float_as_int(x) & 0x80000000) ^ 0x80000000) | 0x3A000000);
}
// exact tie-law bias: +2^-11 if (x<0 || x>=2) else -2^-11.
// Reference law (from floor(x - sign(x)*TINY + 0.5) under RNE): ties toward +inf
// for negatives and positives >= 2 (TINY absorbed); toward -inf for 0 <= x < 2.
// Condition == unsigned bits(x) >= 0x40000000 (no-overflow form, R13-validated).
__device__ __forceinline__ float ebias(float x) {
    unsigned b = (unsigned)__float_as_int(x);
    return __uint_as_float((b >= 0x40000000u) ? 0x3A000000u : 0xBA000000u);
}

// RND: 0 = literal floor path (continuous inputs, layer-0 only)
//      1 = magic round, exact tie law   (grid inputs, any magnitude: L1 encode, b-round)
//      2 = magic round, grid tie law    (grid inputs, |x| < 2: L2 encode, decode)
template<int RND>
__device__ __forceinline__ void cround8p(const float xa[8], const u64 xa2[4], u64 f2[4]) {
#pragma unroll
    for (int p = 0; p < 4; p++) {
        float a0 = xa[2*p], a1 = xa[2*p+1];
        if (RND == 0) {
            u64 v = add2(add2(xa2[p], pk(negtiny(a0), negtiny(a1))), H2C);
            float v0, v1; upk(v, v0, v1);
            f2[p] = pk(floorf(v0), floorf(v1));
        } else {
            u64 b2 = (RND == 1) ? pk(ebias(a0), ebias(a1))
                                : pk(gbias(a0), gbias(a1));
            // (x + bias + MAGIC) - MAGIC : RN-to-int, ties pre-broken by bias.
            f2[p] = add2(add2(add2(xa2[p], b2), MG2C), NMG2C);
        }
    }
}

// first-occurrence argmax scan (R3-proven): sel[j] = first j with |e_j|==m;
// step = sign(e_k), fallback (m==0) step = copysign(1, -xa0).
__device__ __forceinline__ void scanfn(const float e[8], float m, float xa0,
                                       bool sel[8], float& step) {
    bool seen = false;
#pragma unroll
    for (int j = 0; j < 8; j++) {
        bool eq = (fabsf(e[j]) == m);
        sel[j] = eq && !seen;
        seen = seen || eq;
    }
    float t = e[0];
#pragma unroll
    for (int j = 1; j < 8; j++) t = sel[j] ? e[j] : t;
    t = (m == 0.0f) ? -xa0 : t;
    step = copysignf(1.0f, t);
}

// One branch of closest_point_E8, full replication (R7/R13-validated structure).
template<int RND, bool SHIFTED>
__device__ __forceinline__ float e8_branch(const float xa[8], const u64 xa2[4],
                                           const u64 xo2[4], float yc[8]) {
    u64 f2[4];
    cround8p<RND>(xa, xa2, f2);

    float f[8], e[8];
#pragma unroll
    for (int p = 0; p < 4; p++) {
        upk(f2[p], f[2*p], f[2*p+1]);
        u64 e2 = fma2(f2[p], M1C, xa2[p]);   // e = xa - f (single-rounded subtract)
        upk(e2, e[2*p], e[2*p+1]);
    }

    // parity of sum(f): packed tree + magic-add parity extraction.
    // s is an exact integer (|s| << 2^22): bits(s + 1.5*2^23) = 0x4B400000 + s
    // as integer arithmetic; even base -> bit0 == parity of s. Replaces F2I(20cyc).
    u64 s = add2(add2(f2[0], f2[1]), add2(f2[2], f2[3]));
    float sl, sh; upk(s, sl, sh);
    bool odd = (__float_as_int((sl + sh) + MAGF) & 1) != 0;

    // max |e| (FMNMX absorbs |.|)
    float m = fmaxf(fmaxf(fmaxf(fabsf(e[0]),fabsf(e[1])),fmaxf(fabsf(e[2]),fabsf(e[3]))),
                    fmaxf(fmaxf(fabsf(e[4]),fabsf(e[5])),fmaxf(fabsf(e[6]),fabsf(e[7]))));

    bool sel[8]; float step;
    scanfn(e, m, xa[0], sel, step);

    // fold parity into step ONCE (saves 8 per-lane PLOP3s). b + 0.0f is safe:
    // f can never be -0 (magic round emits +0; floor path: -0.5+0.5 -> +0 under RN).
    float step0 = odd ? step : 0.0f;

    // candidate assembly (base = f (+0.5 if SHIFTED), flip selected coord)
#pragma unroll
    for (int p = 0; p < 4; p++) {
        float b0, b1;
        if (SHIFTED) { u64 b2 = add2(f2[p], H2C); upk(b2, b0, b1); }
        else         { b0 = f[2*p]; b1 = f[2*p+1]; }
        yc[2*p]   = sel[2*p]   ? (b0 + step0) : b0;
        yc[2*p+1] = sel[2*p+1] ? (b1 + step0) : b1;
    }

    // distance vs ORIGINAL x: packed residuals, scalar sequential sum (reference order)
    float r[8];
#pragma unroll
    for (int p = 0; p < 4; p++) {
        u64 r2 = fma2(pk(yc[2*p], yc[2*p+1]), M1C, xo2[p]);
        upk(r2, r[2*p], r[2*p+1]);
    }
    float d = r[0] * r[0];
#pragma unroll
    for (int j = 1; j < 8; j++) d = fmaf(r[j], r[j], d);
    return d;
}

template<int RND>
__device__ __forceinline__ void cp_e8(const float x[8], float y[8]) {
    u64 x2[4], xs2[4];
    float xs[8];
#pragma unroll
    for (int p = 0; p < 4; p++) {
        x2[p] = pk(x[2*p], x[2*p+1]);
        xs2[p] = add2(x2[p], NH2C);            // x - 0.5, packed (== scalar)
        upk(xs2[p], xs[2*p], xs[2*p+1]);
    }
    float yA[8], yB[8];
    float dA = e8_branch<RND, false>(x,  x2,  x2, yA);
    float dB = e8_branch<RND, true >(xs, xs2, x2, yB);
    bool pickA = dA < dB;                      // tie -> B (jnp.where(d0 < d1, y0, y1))
#pragma unroll
    for (int j = 0; j < 8; j++) y[j] = pickA ? yA[j] : yB[j];
}

__global__ __launch_bounds__(128)   // natural regs — forced caps spill (R8/R10)
void LatticeQuantizer_kernel(const float* __restrict__ x,
                             float* __restrict__ out, int N)
{
    int i = blockIdx.x * blockDim.x + threadIdx.x;
    if (i >= N) return;

    float beta = c_beta;

    float4 va = ((const float4*)x)[2 * i];
    float4 vb = ((const float4*)x)[2 * i + 1];
    float xl[8] = {va.x, va.y, va.z, va.w, vb.x, vb.y, vb.z, vb.w};
    if (beta != 1.0f) {             // uniform branch; x/1.0 == x exactly
#pragma unroll
        for (int j = 0; j < 8; j++) xl[j] = __fdiv_rn(xl[j], beta);
    }

    u64 xh2[4];

#pragma unroll
    for (int m = 0; m < 3; m++) {
        // ---- encode: yq = closest_point_E8(xl + eps) ----
        float xe[8], yq[8];
#pragma unroll
        for (int p = 0; p < 4; p++) {
            u64 t = add2(pk(xl[2*p], xl[2*p+1]), c_eps2[p]);
            upk(t, xe[2*p], xe[2*p+1]);
        }
        // layer 0: continuous -> literal floor path.
        // layer 1: 1/8-grid, |xe| can exceed 2 -> magic + exact tie law.
        // layer 2: 1/8-grid, |xe| < 2 -> magic + grid tie law (R13-validated).
        if (m == 0)      cp_e8<0>(xe, yq);
        else if (m == 1) cp_e8<1>(xe, yq);
        else             cp_e8<2>(xe, yq);

        // ---- acc = yq @ G_inv via exact forward substitution (acc @ Gm = yq) ----
        float a[8];
        a[0] = 0.5f * yq[0];
#pragma unroll
        for (int j = 1; j < 7; j++) a[j] = a[j - 1] + yq[j];
        float s06 = ((a[0] + a[1]) + (a[2] + a[3])) + ((a[4] + a[5]) + a[6]);
        a[7] = fmaf(2.0f, yq[7], -s06);

        // ---- b = custom_round(fmod(acc,4)): r quarter-int in (-4,4);
        //      ties follow the exact tie law -> magic RND=1 (R13-validated) ----
        float r8[8], bv[8];
        u64 r82[4], bv2[4];
#pragma unroll
        for (int j = 0; j < 8; j++)
            r8[j] = fmaf(-4.0f, truncf(a[j] * 0.25f), a[j]);  // == fmodf(a,4) exactly
#pragma unroll
        for (int p = 0; p < 4; p++) r82[p] = pk(r8[2*p], r8[2*p+1]);
        cround8p<1>(r8, r82, bv2);
#pragma unroll
        for (int p = 0; p < 4; p++) upk(bv2[p], bv[2*p], bv[2*p+1]);

        // ---- next layer input: xl = yq * 0.25 (packed, exact) ----
#pragma unroll
        for (int p = 0; p < 4; p++) {
            u64 t = mul2(pk(yq[2*p], yq[2*p+1]), QC);
            upk(t, xl[2*p], xl[2*p+1]);
        }

        // ---- Gb = b @ G.T, sparse exact form ----
        float gb[8];
        {
            float h = 0.5f * bv[7];
            gb[0] = fmaf(2.0f, bv[0], -bv[1]) + h;
#pragma unroll
            for (int j = 1; j < 6; j++) gb[j] = (bv[j] - bv[j + 1]) + h;
            gb[6] = bv[6] + h;
            gb[7] = h;
        }

        // ---- x_i = Gb - 4*closest_point_E8(Gb/4);  xh += 4^m * x_i ----
        // gq in [-0.75, 1.875], branch-B in [-1.25, 1.375] -> grid tie law.
        float gq[8], cpv[8];
        u64 gb2[4];
#pragma unroll
        for (int p = 0; p < 4; p++) {
            gb2[p] = pk(gb[2*p], gb[2*p+1]);
            u64 t = mul2(gb2[p], QC);
            upk(t, gq[2*p], gq[2*p+1]);
        }
        cp_e8<2>(gq, cpv);

#pragma unroll
        for (int p = 0; p < 4; p++) {
            u64 xi = fma2(pk(cpv[2*p], cpv[2*p+1]), M4C, gb2[p]);
            if (m == 0)      xh2[p] = xi;
            else if (m == 1) xh2[p] = fma2(xi, S4C,  xh2[p]);   // exact dyadics
            else             xh2[p] = fma2(xi, S16C, xh2[p]);
        }
    }

    u64 bb = pk(beta, beta);
    float o[8];
#pragma unroll
    for (int p = 0; p < 4; p++) {
        u64 t = mul2(xh2[p], bb);
        upk(t, o[2*p], o[2*p+1]);
    }
    float4 o0 = {o[0], o[1], o[2], o[3]};
    float4 o1 = {o[4], o[5], o[6], o[7]};
    ((float4*)out)[2 * i]     = o0;
    ((float4*)out)[2 * i + 1] = o1;
}

extern "C" void kernel_launch(void* const* d_in, const int* in_sizes, int n_in,
                              void* d_out, int out_size) {
    const float* x = (const float*)d_in[0];
    float* out = (float*)d_out;

    // beta + eps into constant bank (D2D async copies: graph-capturable, no alloc)
    cudaMemcpyToSymbolAsync(c_beta, d_in[1], sizeof(float), 0,
                            cudaMemcpyDeviceToDevice, 0);
    cudaMemcpyToSymbolAsync(c_eps2, d_in[4], 8 * sizeof(float), 0,
                            cudaMemcpyDeviceToDevice, 0);

    int N = in_sizes[0] / 8;
    int threads = 128;
    int blocks = (N + threads - 1) / threads;
    LatticeQuantizer_kernel<<<blocks, threads>>>(x, out, N);
}